// round 2
// baseline (speedup 1.0000x reference)
#include <cuda_runtime.h>
#include <cuda_bf16.h>

// Problem constants (fixed by the dataset)
constexpr int Bv  = 4;
constexpr int Lv  = 2048;
constexpr int Dv  = 1024;
constexpr int MR  = 512;
constexpr int TAB = 2 * MR + 1;   // 1025
constexpr int ROWS = Bv * Lv;     // 8192

// GEMM tiling
#define BM 128
#define BN 128
#define BK 16
#define TM 8
#define TN 8
// 256 threads: 16x16 thread grid, each 8x8 outputs

// Scratch (allocation-free rule: __device__ globals)
__device__ float g_Q[(size_t)ROWS * Dv];          // 32 MB
__device__ float g_K[(size_t)ROWS * Dv];          // 32 MB
__device__ float g_R[(size_t)TAB * Dv];           // 4.2 MB
__device__ float g_A[(size_t)ROWS * TAB];         // 33.6 MB

// ---------------------------------------------------------------------------
// Generic NT SGEMM: C[M,N] = (A + bias) * B^T
//   A: M x K row-major, B: N x K row-major, bias: length-K broadcast over rows
//   K must be a multiple of BK and of 4 (true here: K=1024).
// ---------------------------------------------------------------------------
template <bool HAS_BIAS>
__global__ void __launch_bounds__(256, 2) sgemm_nt(
    const float* __restrict__ A, const float* __restrict__ B,
    const float* __restrict__ bias, float* __restrict__ C,
    int M, int N, int K)
{
    __shared__ float As[BK][BM];
    __shared__ float Bs[BK][BN];

    const int brow = blockIdx.y * BM;
    const int bcol = blockIdx.x * BN;
    const int tid  = threadIdx.x;
    const int tx   = tid & 15;   // 0..15 -> col group
    const int ty   = tid >> 4;   // 0..15 -> row group

    float acc[TM][TN];
#pragma unroll
    for (int i = 0; i < TM; ++i)
#pragma unroll
        for (int j = 0; j < TN; ++j) acc[i][j] = 0.f;

    for (int k0 = 0; k0 < K; k0 += BK) {
        // Load tiles: 512 float4 per matrix, 256 threads -> 2 each
#pragma unroll
        for (int it = 0; it < 2; ++it) {
            const int lin = tid + it * 256;      // float4 slot 0..511
            const int row = lin >> 2;            // 0..127
            const int kq  = (lin & 3) * 4;       // 0,4,8,12

            // A tile (row = M-row)
            float4 va = make_float4(0.f, 0.f, 0.f, 0.f);
            const int gr = brow + row;
            if (gr < M)
                va = *reinterpret_cast<const float4*>(&A[(size_t)gr * K + k0 + kq]);
            if (HAS_BIAS) {
                const float4 vb = *reinterpret_cast<const float4*>(&bias[k0 + kq]);
                va.x += vb.x; va.y += vb.y; va.z += vb.z; va.w += vb.w;
            }
            As[kq + 0][row] = va.x;
            As[kq + 1][row] = va.y;
            As[kq + 2][row] = va.z;
            As[kq + 3][row] = va.w;

            // B tile (row = N-row)
            float4 wb = make_float4(0.f, 0.f, 0.f, 0.f);
            const int gc = bcol + row;
            if (gc < N)
                wb = *reinterpret_cast<const float4*>(&B[(size_t)gc * K + k0 + kq]);
            Bs[kq + 0][row] = wb.x;
            Bs[kq + 1][row] = wb.y;
            Bs[kq + 2][row] = wb.z;
            Bs[kq + 3][row] = wb.w;
        }
        __syncthreads();

#pragma unroll
        for (int kk = 0; kk < BK; ++kk) {
            float ra[TM], rb[TN];
#pragma unroll
            for (int i = 0; i < TM; ++i) ra[i] = As[kk][ty * TM + i];
#pragma unroll
            for (int j = 0; j < TN; ++j) rb[j] = Bs[kk][tx * TN + j];
#pragma unroll
            for (int i = 0; i < TM; ++i)
#pragma unroll
                for (int j = 0; j < TN; ++j)
                    acc[i][j] = fmaf(ra[i], rb[j], acc[i][j]);
        }
        __syncthreads();
    }

#pragma unroll
    for (int i = 0; i < TM; ++i) {
        const int r = brow + ty * TM + i;
        if (r >= M) continue;
#pragma unroll
        for (int j = 0; j < TN; ++j) {
            const int c = bcol + tx * TN + j;
            if (c < N) C[(size_t)r * N + c] = acc[i][j];
        }
    }
}

// ---------------------------------------------------------------------------
// Content kernel: per batch b,
//   out[b,i,j] = ( sum_d (Q[b,i,d]+u[d]) * K[b,j,d]  +  A[b,i, clip(i-j)+MR] ) / 32
// M = N = 2048 (divisible by tile), K = 1024.
// ---------------------------------------------------------------------------
__global__ void __launch_bounds__(256, 2) content_kernel(
    const float* __restrict__ Qg, const float* __restrict__ Kg,
    const float* __restrict__ u,  const float* __restrict__ Ag,
    float* __restrict__ out)
{
    const int b = blockIdx.z;
    const float* Aop = Qg + (size_t)b * Lv * Dv;
    const float* Bop = Kg + (size_t)b * Lv * Dv;

    __shared__ float As[BK][BM];
    __shared__ float Bs[BK][BN];

    const int brow = blockIdx.y * BM;
    const int bcol = blockIdx.x * BN;
    const int tid  = threadIdx.x;
    const int tx   = tid & 15;
    const int ty   = tid >> 4;

    float acc[TM][TN];
#pragma unroll
    for (int i = 0; i < TM; ++i)
#pragma unroll
        for (int j = 0; j < TN; ++j) acc[i][j] = 0.f;

    for (int k0 = 0; k0 < Dv; k0 += BK) {
#pragma unroll
        for (int it = 0; it < 2; ++it) {
            const int lin = tid + it * 256;
            const int row = lin >> 2;
            const int kq  = (lin & 3) * 4;

            float4 va = *reinterpret_cast<const float4*>(&Aop[(size_t)(brow + row) * Dv + k0 + kq]);
            const float4 vb = *reinterpret_cast<const float4*>(&u[k0 + kq]);
            va.x += vb.x; va.y += vb.y; va.z += vb.z; va.w += vb.w;
            As[kq + 0][row] = va.x;
            As[kq + 1][row] = va.y;
            As[kq + 2][row] = va.z;
            As[kq + 3][row] = va.w;

            const float4 wb = *reinterpret_cast<const float4*>(&Bop[(size_t)(bcol + row) * Dv + k0 + kq]);
            Bs[kq + 0][row] = wb.x;
            Bs[kq + 1][row] = wb.y;
            Bs[kq + 2][row] = wb.z;
            Bs[kq + 3][row] = wb.w;
        }
        __syncthreads();

#pragma unroll
        for (int kk = 0; kk < BK; ++kk) {
            float ra[TM], rb[TN];
#pragma unroll
            for (int i = 0; i < TM; ++i) ra[i] = As[kk][ty * TM + i];
#pragma unroll
            for (int j = 0; j < TN; ++j) rb[j] = Bs[kk][tx * TN + j];
#pragma unroll
            for (int i = 0; i < TM; ++i)
#pragma unroll
                for (int j = 0; j < TN; ++j)
                    acc[i][j] = fmaf(ra[i], rb[j], acc[i][j]);
        }
        __syncthreads();
    }

    // Epilogue: gather relative-position scores and scale by 1/sqrt(1024) = 1/32
    const float scale = 0.03125f;
#pragma unroll
    for (int i = 0; i < TM; ++i) {
        const int r = brow + ty * TM + i;
        const float* Arow = Ag + ((size_t)b * Lv + r) * TAB;
        float* Orow = out + ((size_t)b * Lv + r) * Lv;
#pragma unroll
        for (int j = 0; j < TN; ++j) {
            const int c = bcol + tx * TN + j;
            int rel = r - c;
            rel = rel < -MR ? -MR : (rel > MR ? MR : rel);
            const float pos = Arow[rel + MR];
            Orow[c] = (acc[i][j] + pos) * scale;
        }
    }
}

// ---------------------------------------------------------------------------
// Launch
// ---------------------------------------------------------------------------
extern "C" void kernel_launch(void* const* d_in, const int* in_sizes, int n_in,
                              void* d_out, int out_size)
{
    const float* x     = (const float*)d_in[0];
    const float* Wq    = (const float*)d_in[1];
    const float* Wk    = (const float*)d_in[2];
    const float* Wr    = (const float*)d_in[3];
    const float* u     = (const float*)d_in[4];
    const float* v     = (const float*)d_in[5];
    const float* table = (const float*)d_in[6];
    float* out = (float*)d_out;

    float *Qp, *Kp, *Rp, *Ap;
    cudaGetSymbolAddress((void**)&Qp, g_Q);
    cudaGetSymbolAddress((void**)&Kp, g_K);
    cudaGetSymbolAddress((void**)&Rp, g_R);
    cudaGetSymbolAddress((void**)&Ap, g_A);

    const dim3 blk(256);

    // Q = x Wq^T, K = x Wk^T  : M=8192, N=1024, K=1024
    {
        dim3 grid(Dv / BN, ROWS / BM);
        sgemm_nt<false><<<grid, blk>>>(x, Wq, nullptr, Qp, ROWS, Dv, Dv);
        sgemm_nt<false><<<grid, blk>>>(x, Wk, nullptr, Kp, ROWS, Dv, Dv);
    }
    // R = table Wr^T : M=1025, N=1024, K=1024
    {
        dim3 grid(Dv / BN, (TAB + BM - 1) / BM);
        sgemm_nt<false><<<grid, blk>>>(table, Wr, nullptr, Rp, TAB, Dv, Dv);
    }
    // A = (Q+v) R^T : M=8192, N=1025, K=1024
    {
        dim3 grid((TAB + BN - 1) / BN, ROWS / BM);
        sgemm_nt<true><<<grid, blk>>>(Qp, Rp, v, Ap, ROWS, TAB, Dv);
    }
    // out = ((Q+u) K^T + gather(A)) / 32 : per batch 2048x2048, K=1024
    {
        dim3 grid(Lv / BN, Lv / BM, Bv);
        content_kernel<<<grid, blk>>>(Qp, Kp, u, Ap, out);
    }
    (void)in_sizes; (void)n_in; (void)out_size;
}

// round 4
// speedup vs baseline: 1.8488x; 1.8488x over previous
#include <cuda_runtime.h>
#include <cuda_bf16.h>
#include <cstdint>

// ---------------------------------------------------------------- constants
constexpr int Bv = 4, Lv = 2048, Dv = 1024, MR = 512;
constexpr int TAB = 2 * MR + 1;      // 1025
constexpr int ROWS = Bv * Lv;        // 8192
constexpr int K3 = 3 * Dv;           // 3072 (hi|hi|lo packed K)

// Tile config
constexpr int BM = 128, BN = 128, BK = 32;   // bf16 elements
constexpr int STAGES = 3;
constexpr int NKS = K3 / BK;                 // 96
constexpr int ROWB = 80;                     // smem row stride bytes (32*2 + 16 pad)
constexpr int B_OFF = BM * ROWB;             // 10240
constexpr int STAGE_BYTES = (BM + BN) * ROWB;  // 20480
constexpr int SMEM_DYN = STAGES * STAGE_BYTES; // 61440

constexpr int TAB_PAD = 1152;        // 9*128 padding for table/R rows
constexpr int LDSC = 1028;           // A_scores row stride (16B aligned)

// ---------------------------------------------------------------- scratch
__device__ __nv_bfloat16 g_xpA[(size_t)ROWS * K3];
__device__ __nv_bfloat16 g_WqB[(size_t)Dv * K3];
__device__ __nv_bfloat16 g_WkB[(size_t)Dv * K3];
__device__ __nv_bfloat16 g_WrB[(size_t)Dv * K3];
__device__ __nv_bfloat16 g_tabA[(size_t)TAB_PAD * K3];
__device__ float         g_Q[(size_t)ROWS * Dv];
__device__ float         g_K[(size_t)ROWS * Dv];
__device__ float         g_R[(size_t)TAB * Dv];
__device__ __nv_bfloat16 g_QvA[(size_t)ROWS * K3];
__device__ __nv_bfloat16 g_QuA[(size_t)ROWS * K3];
__device__ __nv_bfloat16 g_KB[(size_t)ROWS * K3];
__device__ __nv_bfloat16 g_RB[(size_t)TAB_PAD * K3];
__device__ float         g_SC[(size_t)ROWS * LDSC];

// ---------------------------------------------------------------- PTX utils
__device__ __forceinline__ uint32_t smem_u32(const void* p) {
    uint32_t a;
    asm("{ .reg .u64 t; cvta.to.shared.u64 t, %1; cvt.u32.u64 %0, t; }" : "=r"(a) : "l"(p));
    return a;
}
__device__ __forceinline__ void cp_async16(uint32_t s, const void* g) {
    asm volatile("cp.async.cg.shared.global [%0], [%1], 16;" :: "r"(s), "l"(g));
}
#define CP_COMMIT() asm volatile("cp.async.commit_group;" ::: "memory")
#define CP_WAIT1()  asm volatile("cp.async.wait_group 1;" ::: "memory")

__device__ __forceinline__ void ldm_x4(uint32_t* r, uint32_t a) {
    asm volatile("ldmatrix.sync.aligned.m8n8.x4.shared.b16 {%0,%1,%2,%3}, [%4];"
                 : "=r"(r[0]), "=r"(r[1]), "=r"(r[2]), "=r"(r[3]) : "r"(a));
}
__device__ __forceinline__ void ldm_x2(uint32_t* r, uint32_t a) {
    asm volatile("ldmatrix.sync.aligned.m8n8.x2.shared.b16 {%0,%1}, [%2];"
                 : "=r"(r[0]), "=r"(r[1]) : "r"(a));
}
__device__ __forceinline__ void mma16816(float* c, const uint32_t* a, const uint32_t* b) {
    asm volatile("mma.sync.aligned.m16n8k16.row.col.f32.bf16.bf16.f32 "
                 "{%0,%1,%2,%3},{%4,%5,%6,%7},{%8,%9},{%0,%1,%2,%3};"
                 : "+f"(c[0]), "+f"(c[1]), "+f"(c[2]), "+f"(c[3])
                 : "r"(a[0]), "r"(a[1]), "r"(a[2]), "r"(a[3]), "r"(b[0]), "r"(b[1]));
}

// ---------------------------------------------------------------- pack kernels
__device__ __forceinline__ uint32_t bpack(__nv_bfloat16 a, __nv_bfloat16 b) {
    __nv_bfloat162 t; t.x = a; t.y = b;
    return *reinterpret_cast<uint32_t*>(&t);
}

// Split fp32 -> (hi, lo) bf16. A-side layout: [hi | hi | lo]; B-side: [hi | lo | hi].
template <bool BSIDE, bool HASBIAS>
__global__ void pack_kernel(const float* __restrict__ src, const float* __restrict__ bias,
                            __nv_bfloat16* __restrict__ dst, int Mreal, int Mpad)
{
    const size_t total = (size_t)Mpad * (Dv / 4);
    for (size_t i = (size_t)blockIdx.x * blockDim.x + threadIdx.x; i < total;
         i += (size_t)gridDim.x * blockDim.x) {
        const int row = (int)(i / (Dv / 4));
        const int c4  = (int)(i % (Dv / 4)) * 4;
        float4 xv = make_float4(0.f, 0.f, 0.f, 0.f);
        if (row < Mreal) {
            xv = *reinterpret_cast<const float4*>(src + (size_t)row * Dv + c4);
            if (HASBIAS) {
                const float4 bv = *reinterpret_cast<const float4*>(bias + c4);
                xv.x += bv.x; xv.y += bv.y; xv.z += bv.z; xv.w += bv.w;
            }
        }
        __nv_bfloat16 h0 = __float2bfloat16(xv.x), h1 = __float2bfloat16(xv.y);
        __nv_bfloat16 h2 = __float2bfloat16(xv.z), h3 = __float2bfloat16(xv.w);
        __nv_bfloat16 l0 = __float2bfloat16(xv.x - __bfloat162float(h0));
        __nv_bfloat16 l1 = __float2bfloat16(xv.y - __bfloat162float(h1));
        __nv_bfloat16 l2 = __float2bfloat16(xv.z - __bfloat162float(h2));
        __nv_bfloat16 l3 = __float2bfloat16(xv.w - __bfloat162float(h3));
        uint2 hp = make_uint2(bpack(h0, h1), bpack(h2, h3));
        uint2 lp = make_uint2(bpack(l0, l1), bpack(l2, l3));
        __nv_bfloat16* rb = dst + (size_t)row * K3;
        if (BSIDE) {
            *reinterpret_cast<uint2*>(rb + c4)          = hp;
            *reinterpret_cast<uint2*>(rb + Dv + c4)     = lp;
            *reinterpret_cast<uint2*>(rb + 2 * Dv + c4) = hp;
        } else {
            *reinterpret_cast<uint2*>(rb + c4)          = hp;
            *reinterpret_cast<uint2*>(rb + Dv + c4)     = hp;
            *reinterpret_cast<uint2*>(rb + 2 * Dv + c4) = lp;
        }
    }
}

// ---------------------------------------------------------------- GEMM core
// C_tile(128x128) = A(128 x K3) * B(128 x K3)^T, accumulators in registers.
// 8 warps in 2 (M) x 4 (N); warp tile 64x32; m16n8k16 frags 4 (mi) x 4 (ni).
__device__ __forceinline__ void gemm_core(
    const __nv_bfloat16* __restrict__ Abase, const __nv_bfloat16* __restrict__ Bbase,
    uint8_t* dsm, float c[4][4][4])
{
    const int tid = threadIdx.x, lane = tid & 31, wid = tid >> 5;
    const int wm = wid & 1, wn = wid >> 1;
    const uint32_t smem = smem_u32(dsm);

#pragma unroll
    for (int mi = 0; mi < 4; ++mi)
#pragma unroll
        for (int ni = 0; ni < 4; ++ni)
#pragma unroll
            for (int q = 0; q < 4; ++q) c[mi][ni][q] = 0.f;

    // stage loader: 512 16B chunks for A, 512 for B; 4 per thread
    auto load_stage = [&](int s) {
        const uint32_t base = smem + (s % STAGES) * STAGE_BYTES;
#pragma unroll
        for (int it = 0; it < 2; ++it) {
            const int o = tid + it * 256;
            const int r = o >> 2, ch = o & 3;
            cp_async16(base + r * ROWB + ch * 16,
                       Abase + (size_t)r * K3 + s * BK + ch * 8);
        }
#pragma unroll
        for (int it = 0; it < 2; ++it) {
            const int o = tid + it * 256;
            const int r = o >> 2, ch = o & 3;
            cp_async16(base + B_OFF + r * ROWB + ch * 16,
                       Bbase + (size_t)r * K3 + s * BK + ch * 8);
        }
    };

    load_stage(0); CP_COMMIT();
    load_stage(1); CP_COMMIT();

    for (int s = 0; s < NKS; ++s) {
        CP_WAIT1();
        __syncthreads();
        if (s + 2 < NKS) load_stage(s + 2);
        CP_COMMIT();

        const uint32_t sa = smem + (s % STAGES) * STAGE_BYTES;
        const uint32_t sb = sa + B_OFF;
#pragma unroll
        for (int ks = 0; ks < 2; ++ks) {
            uint32_t a[4][4], b[4][2];
#pragma unroll
            for (int mi = 0; mi < 4; ++mi) {
                const uint32_t addr = sa +
                    (uint32_t)((wm * 64 + mi * 16 + (lane & 15)) * ROWB +
                               (ks * 16 + (lane >> 4) * 8) * 2);
                ldm_x4(a[mi], addr);
            }
#pragma unroll
            for (int ni = 0; ni < 4; ++ni) {
                const uint32_t addr = sb +
                    (uint32_t)((wn * 32 + ni * 8 + (lane & 7)) * ROWB +
                               (ks * 16 + ((lane >> 3) & 1) * 8) * 2);
                ldm_x2(b[ni], addr);
            }
#pragma unroll
            for (int mi = 0; mi < 4; ++mi)
#pragma unroll
                for (int ni = 0; ni < 4; ++ni)
                    mma16816(c[mi][ni], a[mi], b[ni]);
        }
    }
}

// ---------------------------------------------------------------- generic GEMM
__global__ void __launch_bounds__(256, 1) gemm3_kernel(
    const __nv_bfloat16* __restrict__ Aop, const __nv_bfloat16* __restrict__ Bop,
    float* __restrict__ C, int Mreal, int Nreal, int ldc)
{
    extern __shared__ uint8_t dsm[];
    const int brow = blockIdx.y * BM;
    const int bcol = blockIdx.x * BN;

    float c[4][4][4];
    gemm_core(Aop + (size_t)brow * K3, Bop + (size_t)bcol * K3, dsm, c);

    const int lane = threadIdx.x & 31, wid = threadIdx.x >> 5;
    const int wm = wid & 1, wn = wid >> 1;
#pragma unroll
    for (int mi = 0; mi < 4; ++mi) {
        const int r0 = brow + wm * 64 + mi * 16 + (lane >> 2);
#pragma unroll
        for (int half = 0; half < 2; ++half) {
            const int r = r0 + half * 8;
            if (r >= Mreal) continue;
            float* crow = C + (size_t)r * ldc;
#pragma unroll
            for (int ni = 0; ni < 4; ++ni) {
                const int col = bcol + wn * 32 + ni * 8 + (lane & 3) * 2;
                const float v0 = c[mi][ni][half * 2 + 0];
                const float v1 = c[mi][ni][half * 2 + 1];
                if (col + 1 < Nreal) {
                    *reinterpret_cast<float2*>(crow + col) = make_float2(v0, v1);
                } else {
                    if (col < Nreal) crow[col] = v0;
                }
            }
        }
    }
}

// ---------------------------------------------------------------- content GEMM
// out[b,i,j] = (sum_d (Q+u)[b,i,d]*K[b,j,d] + SC[b,i, clip(i-j)+MR]) / 32
__global__ void __launch_bounds__(256, 1) content_kernel(
    const __nv_bfloat16* __restrict__ QuA, const __nv_bfloat16* __restrict__ KB,
    const float* __restrict__ SC, float* __restrict__ out)
{
    extern __shared__ uint8_t dsm[];
    const int b = blockIdx.z;
    const int brow = blockIdx.y * BM;
    const int bcol = blockIdx.x * BN;

    float c[4][4][4];
    gemm_core(QuA + ((size_t)(b * Lv + brow)) * K3,
              KB  + ((size_t)(b * Lv + bcol)) * K3, dsm, c);

    const int lane = threadIdx.x & 31, wid = threadIdx.x >> 5;
    const int wm = wid & 1, wn = wid >> 1;
    const float scale = 0.03125f;
#pragma unroll
    for (int mi = 0; mi < 4; ++mi) {
        const int r0 = brow + wm * 64 + mi * 16 + (lane >> 2);
#pragma unroll
        for (int half = 0; half < 2; ++half) {
            const int r = r0 + half * 8;
            const float* srow = SC + ((size_t)(b * Lv + r)) * LDSC;
            float* crow = out + ((size_t)b * Lv + r) * (size_t)Lv;
#pragma unroll
            for (int ni = 0; ni < 4; ++ni) {
                const int col = bcol + wn * 32 + ni * 8 + (lane & 3) * 2;
                int rel0 = r - col, rel1 = r - (col + 1);
                rel0 = rel0 < -MR ? -MR : (rel0 > MR ? MR : rel0);
                rel1 = rel1 < -MR ? -MR : (rel1 > MR ? MR : rel1);
                const float p0 = __ldg(&srow[rel0 + MR]);
                const float p1 = __ldg(&srow[rel1 + MR]);
                const float v0 = (c[mi][ni][half * 2 + 0] + p0) * scale;
                const float v1 = (c[mi][ni][half * 2 + 1] + p1) * scale;
                *reinterpret_cast<float2*>(crow + col) = make_float2(v0, v1);
            }
        }
    }
}

// ---------------------------------------------------------------- launch
extern "C" void kernel_launch(void* const* d_in, const int* in_sizes, int n_in,
                              void* d_out, int out_size)
{
    const float* x     = (const float*)d_in[0];
    const float* Wq    = (const float*)d_in[1];
    const float* Wk    = (const float*)d_in[2];
    const float* Wr    = (const float*)d_in[3];
    const float* u     = (const float*)d_in[4];
    const float* v     = (const float*)d_in[5];
    const float* table = (const float*)d_in[6];
    float* out = (float*)d_out;

    __nv_bfloat16 *xpA, *WqB, *WkB, *WrB, *tabA, *QvA, *QuA, *KB, *RB;
    float *Qp, *Kp, *Rp, *SCp;
    cudaGetSymbolAddress((void**)&xpA, g_xpA);
    cudaGetSymbolAddress((void**)&WqB, g_WqB);
    cudaGetSymbolAddress((void**)&WkB, g_WkB);
    cudaGetSymbolAddress((void**)&WrB, g_WrB);
    cudaGetSymbolAddress((void**)&tabA, g_tabA);
    cudaGetSymbolAddress((void**)&Qp, g_Q);
    cudaGetSymbolAddress((void**)&Kp, g_K);
    cudaGetSymbolAddress((void**)&Rp, g_R);
    cudaGetSymbolAddress((void**)&QvA, g_QvA);
    cudaGetSymbolAddress((void**)&QuA, g_QuA);
    cudaGetSymbolAddress((void**)&KB, g_KB);
    cudaGetSymbolAddress((void**)&RB, g_RB);
    cudaGetSymbolAddress((void**)&SCp, g_SC);

    cudaFuncSetAttribute(gemm3_kernel, cudaFuncAttributeMaxDynamicSharedMemorySize, SMEM_DYN);
    cudaFuncSetAttribute(content_kernel, cudaFuncAttributeMaxDynamicSharedMemorySize, SMEM_DYN);

    const dim3 pblk(256);
    const dim3 pgrd(1024);

    // Pack inputs
    pack_kernel<false, false><<<pgrd, pblk>>>(x, nullptr, xpA, ROWS, ROWS);
    pack_kernel<true,  false><<<pgrd, pblk>>>(Wq, nullptr, WqB, Dv, Dv);
    pack_kernel<true,  false><<<pgrd, pblk>>>(Wk, nullptr, WkB, Dv, Dv);
    pack_kernel<true,  false><<<pgrd, pblk>>>(Wr, nullptr, WrB, Dv, Dv);
    pack_kernel<false, false><<<pgrd, pblk>>>(table, nullptr, tabA, TAB, TAB_PAD);

    // Projections: Q = x Wq^T, K = x Wk^T  (M=8192, N=1024)
    gemm3_kernel<<<dim3(Dv / BN, ROWS / BM), 256, SMEM_DYN>>>(xpA, WqB, Qp, ROWS, Dv, Dv);
    gemm3_kernel<<<dim3(Dv / BN, ROWS / BM), 256, SMEM_DYN>>>(xpA, WkB, Kp, ROWS, Dv, Dv);
    // R = table Wr^T (M=1025 padded to 1152, N=1024)
    gemm3_kernel<<<dim3(Dv / BN, TAB_PAD / BM), 256, SMEM_DYN>>>(tabA, WrB, Rp, TAB, Dv, Dv);

    // Re-pack intermediates
    pack_kernel<false, true ><<<pgrd, pblk>>>(Qp, v, QvA, ROWS, ROWS);
    pack_kernel<false, true ><<<pgrd, pblk>>>(Qp, u, QuA, ROWS, ROWS);
    pack_kernel<true,  false><<<pgrd, pblk>>>(Kp, nullptr, KB, ROWS, ROWS);
    pack_kernel<true,  false><<<pgrd, pblk>>>(Rp, nullptr, RB, TAB, TAB_PAD);

    // A_scores = (Q+v) R^T (M=8192, N=1025 padded to 1152, ldc=1028)
    gemm3_kernel<<<dim3(TAB_PAD / BN, ROWS / BM), 256, SMEM_DYN>>>(QvA, RB, SCp, ROWS, TAB, LDSC);

    // content + gather + scale (per batch 2048x2048)
    content_kernel<<<dim3(Lv / BN, Lv / BM, Bv), 256, SMEM_DYN>>>(QuA, KB, SCp, out);

    (void)in_sizes; (void)n_in; (void)out_size;
}

// round 6
// speedup vs baseline: 3.4125x; 1.8457x over previous
#include <cuda_runtime.h>
#include <cuda_fp16.h>
#include <cstdint>

// ---------------------------------------------------------------- constants
constexpr int Bv = 4, Lv = 2048, Dv = 1024, MR = 512;
constexpr int TAB = 2 * MR + 1;      // 1025
constexpr int ROWS = Bv * Lv;        // 8192
constexpr int K2 = 2 * Dv;           // 2048 (A=[hi|lo], B=[hi|hi])

// Tile config: 256x128 CTA tile, 512 threads (16 warps, 4x4), warp tile 64x32
constexpr int BM = 256, BN = 128, BK = 64;
constexpr int STAGES = 3;
constexpr int NKS = K2 / BK;                   // 32
constexpr int ROWB = 144;                      // 64*2 + 16 pad (conflict-free)
constexpr int B_OFF = BM * ROWB;               // 36864
constexpr int STAGE_BYTES = (BM + BN) * ROWB;  // 55296
constexpr int SMEM_DYN = STAGES * STAGE_BYTES; // 165888

constexpr int TAB_PADM = 1280;       // table rows padded to 5*256 (A/M side)
constexpr int TAB_PADN = 1152;       // R rows padded to 9*128 (B/N side)
constexpr int LDSC = 1028;           // A_scores row stride (16B aligned)

// ---------------------------------------------------------------- scratch
__device__ __half g_xpA[(size_t)ROWS * K2];
__device__ __half g_WqB[(size_t)Dv * K2];
__device__ __half g_WkB[(size_t)Dv * K2];
__device__ __half g_WrB[(size_t)Dv * K2];
__device__ __half g_tabA[(size_t)TAB_PADM * K2];
__device__ float  g_Q[(size_t)ROWS * Dv];
__device__ float  g_K[(size_t)ROWS * Dv];
__device__ float  g_R[(size_t)TAB * Dv];
__device__ __half g_QvA[(size_t)ROWS * K2];
__device__ __half g_QuA[(size_t)ROWS * K2];
__device__ __half g_KB[(size_t)ROWS * K2];
__device__ __half g_RB[(size_t)TAB_PADN * K2];
__device__ float  g_SC[(size_t)ROWS * LDSC];

// ---------------------------------------------------------------- PTX utils
__device__ __forceinline__ uint32_t smem_u32(const void* p) {
    uint32_t a;
    asm("{ .reg .u64 t; cvta.to.shared.u64 t, %1; cvt.u32.u64 %0, t; }" : "=r"(a) : "l"(p));
    return a;
}
__device__ __forceinline__ void cp_async16(uint32_t s, const void* g) {
    asm volatile("cp.async.cg.shared.global [%0], [%1], 16;" :: "r"(s), "l"(g));
}
#define CP_COMMIT() asm volatile("cp.async.commit_group;" ::: "memory")
#define CP_WAIT1()  asm volatile("cp.async.wait_group 1;" ::: "memory")

__device__ __forceinline__ void ldm_x4(uint32_t* r, uint32_t a) {
    asm volatile("ldmatrix.sync.aligned.m8n8.x4.shared.b16 {%0,%1,%2,%3}, [%4];"
                 : "=r"(r[0]), "=r"(r[1]), "=r"(r[2]), "=r"(r[3]) : "r"(a));
}
__device__ __forceinline__ void ldm_x2(uint32_t* r, uint32_t a) {
    asm volatile("ldmatrix.sync.aligned.m8n8.x2.shared.b16 {%0,%1}, [%2];"
                 : "=r"(r[0]), "=r"(r[1]) : "r"(a));
}
__device__ __forceinline__ void mma16816(float* c, const uint32_t* a, const uint32_t* b) {
    asm volatile("mma.sync.aligned.m16n8k16.row.col.f32.f16.f16.f32 "
                 "{%0,%1,%2,%3},{%4,%5,%6,%7},{%8,%9},{%0,%1,%2,%3};"
                 : "+f"(c[0]), "+f"(c[1]), "+f"(c[2]), "+f"(c[3])
                 : "r"(a[0]), "r"(a[1]), "r"(a[2]), "r"(a[3]), "r"(b[0]), "r"(b[1]));
}

// ---------------------------------------------------------------- pack kernels
__device__ __forceinline__ uint32_t hpack(__half a, __half b) {
    __half2 t; t.x = a; t.y = b;
    return *reinterpret_cast<uint32_t*>(&t);
}

// fp16 split: h = fp16(x), l = fp16(x - h). A-side rows: [h | l]; B-side: [h | h].
template <bool BSIDE, bool HASBIAS>
__global__ void pack_kernel(const float* __restrict__ src, const float* __restrict__ bias,
                            __half* __restrict__ dst, int Mreal, int Mpad)
{
    const size_t total = (size_t)Mpad * (Dv / 4);
    for (size_t i = (size_t)blockIdx.x * blockDim.x + threadIdx.x; i < total;
         i += (size_t)gridDim.x * blockDim.x) {
        const int row = (int)(i / (Dv / 4));
        const int c4  = (int)(i % (Dv / 4)) * 4;
        float4 xv = make_float4(0.f, 0.f, 0.f, 0.f);
        if (row < Mreal) {
            xv = *reinterpret_cast<const float4*>(src + (size_t)row * Dv + c4);
            if (HASBIAS) {
                const float4 bv = *reinterpret_cast<const float4*>(bias + c4);
                xv.x += bv.x; xv.y += bv.y; xv.z += bv.z; xv.w += bv.w;
            }
        }
        __half h0 = __float2half_rn(xv.x), h1 = __float2half_rn(xv.y);
        __half h2 = __float2half_rn(xv.z), h3 = __float2half_rn(xv.w);
        uint2 hp = make_uint2(hpack(h0, h1), hpack(h2, h3));
        __half* rb = dst + (size_t)row * K2;
        *reinterpret_cast<uint2*>(rb + c4) = hp;
        if (BSIDE) {
            *reinterpret_cast<uint2*>(rb + Dv + c4) = hp;
        } else {
            __half l0 = __float2half_rn(xv.x - __half2float(h0));
            __half l1 = __float2half_rn(xv.y - __half2float(h1));
            __half l2 = __float2half_rn(xv.z - __half2float(h2));
            __half l3 = __float2half_rn(xv.w - __half2float(h3));
            *reinterpret_cast<uint2*>(rb + Dv + c4) = make_uint2(hpack(l0, l1), hpack(l2, l3));
        }
    }
}

// ---------------------------------------------------------------- GEMM core
// C_tile(256x128) = A(256 x K2) * B(128 x K2)^T, accumulators in registers.
// 16 warps in 4 (M) x 4 (N); warp tile 64x32; m16n8k16 frags 4 (mi) x 4 (ni).
__device__ __forceinline__ void gemm_core(
    const __half* __restrict__ Abase, const __half* __restrict__ Bbase,
    uint8_t* dsm, float c[4][4][4])
{
    const int tid = threadIdx.x, lane = tid & 31, wid = tid >> 5;
    const int wm = wid & 3, wn = wid >> 2;
    const uint32_t smem = smem_u32(dsm);

#pragma unroll
    for (int mi = 0; mi < 4; ++mi)
#pragma unroll
        for (int ni = 0; ni < 4; ++ni)
#pragma unroll
            for (int q = 0; q < 4; ++q) c[mi][ni][q] = 0.f;

    // stage loader: A 2048 16B chunks, B 1024 chunks; 512 threads
    auto load_stage = [&](int s) {
        const uint32_t base = smem + (s % STAGES) * STAGE_BYTES;
#pragma unroll
        for (int it = 0; it < 4; ++it) {
            const int o = tid + it * 512;
            const int r = o >> 3, ch = o & 7;
            cp_async16(base + r * ROWB + ch * 16,
                       Abase + (size_t)r * K2 + s * BK + ch * 8);
        }
#pragma unroll
        for (int it = 0; it < 2; ++it) {
            const int o = tid + it * 512;
            const int r = o >> 3, ch = o & 7;
            cp_async16(base + B_OFF + r * ROWB + ch * 16,
                       Bbase + (size_t)r * K2 + s * BK + ch * 8);
        }
    };

    load_stage(0); CP_COMMIT();
    load_stage(1); CP_COMMIT();

    for (int s = 0; s < NKS; ++s) {
        CP_WAIT1();
        __syncthreads();
        if (s + 2 < NKS) load_stage(s + 2);
        CP_COMMIT();

        const uint32_t sa = smem + (s % STAGES) * STAGE_BYTES;
        const uint32_t sb = sa + B_OFF;
#pragma unroll
        for (int ks = 0; ks < BK / 16; ++ks) {
            uint32_t a[4][4], b[4][2];
#pragma unroll
            for (int mi = 0; mi < 4; ++mi) {
                const uint32_t addr = sa +
                    (uint32_t)((wm * 64 + mi * 16 + (lane & 15)) * ROWB +
                               ks * 32 + (lane >> 4) * 16);
                ldm_x4(a[mi], addr);
            }
#pragma unroll
            for (int ni = 0; ni < 4; ++ni) {
                const uint32_t addr = sb +
                    (uint32_t)((wn * 32 + ni * 8 + (lane & 7)) * ROWB +
                               ks * 32 + ((lane >> 3) & 1) * 16);
                ldm_x2(b[ni], addr);
            }
#pragma unroll
            for (int mi = 0; mi < 4; ++mi)
#pragma unroll
                for (int ni = 0; ni < 4; ++ni)
                    mma16816(c[mi][ni], a[mi], b[ni]);
        }
    }
}

// ---------------------------------------------------------------- generic GEMM
__global__ void __launch_bounds__(512, 1) gemm2_kernel(
    const __half* __restrict__ Aop, const __half* __restrict__ Bop,
    float* __restrict__ C, int Mreal, int Nreal, int ldc)
{
    extern __shared__ uint8_t dsm[];
    const int brow = blockIdx.y * BM;
    const int bcol = blockIdx.x * BN;

    float c[4][4][4];
    gemm_core(Aop + (size_t)brow * K2, Bop + (size_t)bcol * K2, dsm, c);

    const int lane = threadIdx.x & 31, wid = threadIdx.x >> 5;
    const int wm = wid & 3, wn = wid >> 2;
#pragma unroll
    for (int mi = 0; mi < 4; ++mi) {
        const int r0 = brow + wm * 64 + mi * 16 + (lane >> 2);
#pragma unroll
        for (int half = 0; half < 2; ++half) {
            const int r = r0 + half * 8;
            if (r >= Mreal) continue;
            float* crow = C + (size_t)r * ldc;
#pragma unroll
            for (int ni = 0; ni < 4; ++ni) {
                const int col = bcol + wn * 32 + ni * 8 + (lane & 3) * 2;
                const float v0 = c[mi][ni][half * 2 + 0];
                const float v1 = c[mi][ni][half * 2 + 1];
                if (col + 1 < Nreal) {
                    *reinterpret_cast<float2*>(crow + col) = make_float2(v0, v1);
                } else if (col < Nreal) {
                    crow[col] = v0;
                }
            }
        }
    }
}

// ---------------------------------------------------------------- content GEMM
// out[b,i,j] = (sum_d (Q+u)[b,i,d]*K[b,j,d] + SC[b,i, clip(i-j)+MR]) / 32
__global__ void __launch_bounds__(512, 1) content_kernel(
    const __half* __restrict__ QuA, const __half* __restrict__ KB,
    const float* __restrict__ SC, float* __restrict__ out)
{
    extern __shared__ uint8_t dsm[];
    const int b = blockIdx.z;
    const int brow = blockIdx.y * BM;
    const int bcol = blockIdx.x * BN;

    float c[4][4][4];
    gemm_core(QuA + ((size_t)(b * Lv + brow)) * K2,
              KB  + ((size_t)(b * Lv + bcol)) * K2, dsm, c);

    const int lane = threadIdx.x & 31, wid = threadIdx.x >> 5;
    const int wm = wid & 3, wn = wid >> 2;
    const float scale = 0.03125f;
#pragma unroll
    for (int mi = 0; mi < 4; ++mi) {
        const int r0 = brow + wm * 64 + mi * 16 + (lane >> 2);
#pragma unroll
        for (int half = 0; half < 2; ++half) {
            const int r = r0 + half * 8;
            const float* srow = SC + ((size_t)(b * Lv + r)) * LDSC;
            float* crow = out + ((size_t)b * Lv + r) * (size_t)Lv;
#pragma unroll
            for (int ni = 0; ni < 4; ++ni) {
                const int col = bcol + wn * 32 + ni * 8 + (lane & 3) * 2;
                int rel0 = r - col, rel1 = rel0 - 1;
                rel0 = rel0 < -MR ? -MR : (rel0 > MR ? MR : rel0);
                rel1 = rel1 < -MR ? -MR : (rel1 > MR ? MR : rel1);
                const float p0 = __ldg(&srow[rel0 + MR]);
                const float p1 = __ldg(&srow[rel1 + MR]);
                const float v0 = (c[mi][ni][half * 2 + 0] + p0) * scale;
                const float v1 = (c[mi][ni][half * 2 + 1] + p1) * scale;
                *reinterpret_cast<float2*>(crow + col) = make_float2(v0, v1);
            }
        }
    }
}

// ---------------------------------------------------------------- launch
extern "C" void kernel_launch(void* const* d_in, const int* in_sizes, int n_in,
                              void* d_out, int out_size)
{
    const float* x     = (const float*)d_in[0];
    const float* Wq    = (const float*)d_in[1];
    const float* Wk    = (const float*)d_in[2];
    const float* Wr    = (const float*)d_in[3];
    const float* u     = (const float*)d_in[4];
    const float* v     = (const float*)d_in[5];
    const float* table = (const float*)d_in[6];
    float* out = (float*)d_out;

    __half *xpA, *WqB, *WkB, *WrB, *tabA, *QvA, *QuA, *KB, *RB;
    float *Qp, *Kp, *Rp, *SCp;
    cudaGetSymbolAddress((void**)&xpA, g_xpA);
    cudaGetSymbolAddress((void**)&WqB, g_WqB);
    cudaGetSymbolAddress((void**)&WkB, g_WkB);
    cudaGetSymbolAddress((void**)&WrB, g_WrB);
    cudaGetSymbolAddress((void**)&tabA, g_tabA);
    cudaGetSymbolAddress((void**)&Qp, g_Q);
    cudaGetSymbolAddress((void**)&Kp, g_K);
    cudaGetSymbolAddress((void**)&Rp, g_R);
    cudaGetSymbolAddress((void**)&QvA, g_QvA);
    cudaGetSymbolAddress((void**)&QuA, g_QuA);
    cudaGetSymbolAddress((void**)&KB, g_KB);
    cudaGetSymbolAddress((void**)&RB, g_RB);
    cudaGetSymbolAddress((void**)&SCp, g_SC);

    cudaFuncSetAttribute(gemm2_kernel, cudaFuncAttributeMaxDynamicSharedMemorySize, SMEM_DYN);
    cudaFuncSetAttribute(content_kernel, cudaFuncAttributeMaxDynamicSharedMemorySize, SMEM_DYN);

    const dim3 pblk(256);
    const dim3 pgrd(1024);

    // Pack inputs
    pack_kernel<false, false><<<pgrd, pblk>>>(x, nullptr, xpA, ROWS, ROWS);
    pack_kernel<true,  false><<<pgrd, pblk>>>(Wq, nullptr, WqB, Dv, Dv);
    pack_kernel<true,  false><<<pgrd, pblk>>>(Wk, nullptr, WkB, Dv, Dv);
    pack_kernel<true,  false><<<pgrd, pblk>>>(Wr, nullptr, WrB, Dv, Dv);
    pack_kernel<false, false><<<pgrd, pblk>>>(table, nullptr, tabA, TAB, TAB_PADM);

    // Projections: Q = x Wq^T, K = x Wk^T  (M=8192, N=1024)
    gemm2_kernel<<<dim3(Dv / BN, ROWS / BM), 512, SMEM_DYN>>>(xpA, WqB, Qp, ROWS, Dv, Dv);
    gemm2_kernel<<<dim3(Dv / BN, ROWS / BM), 512, SMEM_DYN>>>(xpA, WkB, Kp, ROWS, Dv, Dv);
    // R = table Wr^T (M=1025 padded to 1280, N=1024)
    gemm2_kernel<<<dim3(Dv / BN, TAB_PADM / BM), 512, SMEM_DYN>>>(tabA, WrB, Rp, TAB, Dv, Dv);

    // Re-pack intermediates
    pack_kernel<false, true ><<<pgrd, pblk>>>(Qp, v, QvA, ROWS, ROWS);
    pack_kernel<false, true ><<<pgrd, pblk>>>(Qp, u, QuA, ROWS, ROWS);
    pack_kernel<true,  false><<<pgrd, pblk>>>(Kp, nullptr, KB, ROWS, ROWS);
    pack_kernel<true,  false><<<pgrd, pblk>>>(Rp, nullptr, RB, TAB, TAB_PADN);

    // A_scores = (Q+v) R^T (M=8192, N=1025 padded to 1152, ldc=1028)
    gemm2_kernel<<<dim3(TAB_PADN / BN, ROWS / BM), 512, SMEM_DYN>>>(QvA, RB, SCp, ROWS, TAB, LDSC);

    // content + gather + scale (per batch 2048x2048)
    content_kernel<<<dim3(Lv / BN, Lv / BM, Bv), 512, SMEM_DYN>>>(QuA, KB, SCp, out);

    (void)in_sizes; (void)n_in; (void)out_size;
}

// round 7
// speedup vs baseline: 3.4753x; 1.0184x over previous
#include <cuda_runtime.h>
#include <cuda_fp16.h>
#include <cstdint>

// ---------------------------------------------------------------- constants
constexpr int Bv = 4, Lv = 2048, Dv = 1024, MR = 512;
constexpr int TAB = 2 * MR + 1;      // 1025
constexpr int ROWS = Bv * Lv;        // 8192
constexpr int K2 = 2 * Dv;           // 2048 (A=[hi|lo], B=[hi|hi])

// Tile config: 256x128 CTA tile, 256 threads (8 warps, 4Mx2N), warp tile 64x64
constexpr int BM = 256, BN = 128, BK = 64;
constexpr int STAGES = 3;
constexpr int NKS = K2 / BK;                   // 32
constexpr int ROWB = 144;                      // 64*2 + 16 pad (conflict-free)
constexpr int B_OFF = BM * ROWB;               // 36864
constexpr int STAGE_BYTES = (BM + BN) * ROWB;  // 55296
constexpr int SMEM_DYN = STAGES * STAGE_BYTES; // 165888

constexpr int TAB_PADM = 1280;       // table rows padded to 5*256 (A/M side)
constexpr int TAB_PADN = 1152;       // R rows padded to 9*128 (B/N side)
constexpr int LDSC = 1028;           // A_scores row stride (16B aligned)

// ---------------------------------------------------------------- scratch
__device__ __half g_xpA[(size_t)ROWS * K2];
__device__ __half g_WqB[(size_t)Dv * K2];
__device__ __half g_WkB[(size_t)Dv * K2];
__device__ __half g_WrB[(size_t)Dv * K2];
__device__ __half g_tabA[(size_t)TAB_PADM * K2];
__device__ __half g_QvA[(size_t)ROWS * K2];
__device__ __half g_QuA[(size_t)ROWS * K2];
__device__ __half g_KB[(size_t)ROWS * K2];
__device__ __half g_RB[(size_t)TAB_PADN * K2];   // zero-init covers pad rows
__device__ float  g_SC[(size_t)ROWS * LDSC];

// ---------------------------------------------------------------- PTX utils
__device__ __forceinline__ uint32_t smem_u32(const void* p) {
    uint32_t a;
    asm("{ .reg .u64 t; cvta.to.shared.u64 t, %1; cvt.u32.u64 %0, t; }" : "=r"(a) : "l"(p));
    return a;
}
__device__ __forceinline__ void cp_async16(uint32_t s, const void* g) {
    asm volatile("cp.async.cg.shared.global [%0], [%1], 16;" :: "r"(s), "l"(g));
}
#define CP_COMMIT() asm volatile("cp.async.commit_group;" ::: "memory")
#define CP_WAIT1()  asm volatile("cp.async.wait_group 1;" ::: "memory")

__device__ __forceinline__ void ldm_x4(uint32_t* r, uint32_t a) {
    asm volatile("ldmatrix.sync.aligned.m8n8.x4.shared.b16 {%0,%1,%2,%3}, [%4];"
                 : "=r"(r[0]), "=r"(r[1]), "=r"(r[2]), "=r"(r[3]) : "r"(a));
}
__device__ __forceinline__ void mma16816(float* c, const uint32_t* a, const uint32_t* b) {
    asm volatile("mma.sync.aligned.m16n8k16.row.col.f32.f16.f16.f32 "
                 "{%0,%1,%2,%3},{%4,%5,%6,%7},{%8,%9},{%0,%1,%2,%3};"
                 : "+f"(c[0]), "+f"(c[1]), "+f"(c[2]), "+f"(c[3])
                 : "r"(a[0]), "r"(a[1]), "r"(a[2]), "r"(a[3]), "r"(b[0]), "r"(b[1]));
}

// ---------------------------------------------------------------- pack kernels
__device__ __forceinline__ uint32_t hpack(__half a, __half b) {
    __half2 t; t.x = a; t.y = b;
    return *reinterpret_cast<uint32_t*>(&t);
}

// fp16 split: h = fp16(x), l = fp16(x - h). A-side rows: [h | l]; B-side: [h | h].
template <bool BSIDE>
__global__ void pack_kernel(const float* __restrict__ src, __half* __restrict__ dst,
                            int Mreal, int Mpad)
{
    const size_t total = (size_t)Mpad * (Dv / 4);
    for (size_t i = (size_t)blockIdx.x * blockDim.x + threadIdx.x; i < total;
         i += (size_t)gridDim.x * blockDim.x) {
        const int row = (int)(i / (Dv / 4));
        const int c4  = (int)(i % (Dv / 4)) * 4;
        float4 xv = make_float4(0.f, 0.f, 0.f, 0.f);
        if (row < Mreal)
            xv = *reinterpret_cast<const float4*>(src + (size_t)row * Dv + c4);
        __half h0 = __float2half_rn(xv.x), h1 = __float2half_rn(xv.y);
        __half h2 = __float2half_rn(xv.z), h3 = __float2half_rn(xv.w);
        uint2 hp = make_uint2(hpack(h0, h1), hpack(h2, h3));
        __half* rb = dst + (size_t)row * K2;
        *reinterpret_cast<uint2*>(rb + c4) = hp;
        if (BSIDE) {
            *reinterpret_cast<uint2*>(rb + Dv + c4) = hp;
        } else {
            __half l0 = __float2half_rn(xv.x - __half2float(h0));
            __half l1 = __float2half_rn(xv.y - __half2float(h1));
            __half l2 = __float2half_rn(xv.z - __half2float(h2));
            __half l3 = __float2half_rn(xv.w - __half2float(h3));
            *reinterpret_cast<uint2*>(rb + Dv + c4) = make_uint2(hpack(l0, l1), hpack(l2, l3));
        }
    }
}

// ---------------------------------------------------------------- GEMM core
// C_tile(256x128) = A(256 x K2) * B(128 x K2)^T, accumulators in registers.
// 8 warps in 4 (M) x 2 (N); warp tile 64x64; frags 4 (mi) x 8 (nj n8-groups).
__device__ __forceinline__ void gemm_core(
    const __half* __restrict__ Abase, const __half* __restrict__ Bbase,
    uint8_t* dsm, float c[4][8][4])
{
    const int tid = threadIdx.x, lane = tid & 31, wid = tid >> 5;
    const int wm = wid & 3, wn = wid >> 2;
    const uint32_t smem = smem_u32(dsm);

#pragma unroll
    for (int mi = 0; mi < 4; ++mi)
#pragma unroll
        for (int nj = 0; nj < 8; ++nj)
#pragma unroll
            for (int q = 0; q < 4; ++q) c[mi][nj][q] = 0.f;

    // stage loader: A 2048 16B chunks (8/thread), B 1024 (4/thread); 256 threads
    auto load_stage = [&](int s) {
        const uint32_t base = smem + (s % STAGES) * STAGE_BYTES;
#pragma unroll
        for (int it = 0; it < 8; ++it) {
            const int o = tid + it * 256;
            const int r = o >> 3, ch = o & 7;
            cp_async16(base + r * ROWB + ch * 16,
                       Abase + (size_t)r * K2 + s * BK + ch * 8);
        }
#pragma unroll
        for (int it = 0; it < 4; ++it) {
            const int o = tid + it * 256;
            const int r = o >> 3, ch = o & 7;
            cp_async16(base + B_OFF + r * ROWB + ch * 16,
                       Bbase + (size_t)r * K2 + s * BK + ch * 8);
        }
    };

    load_stage(0); CP_COMMIT();
    load_stage(1); CP_COMMIT();

    // ldmatrix lane-address components (constant across stages)
    const int a_row = wm * 64 + (lane & 15);       // + mi*16
    const int a_koff = (lane >> 4) * 16;           // bytes
    const int b_row = wn * 64 + (lane & 7) + ((lane >> 4) & 1) * 8;  // + ni*16
    const int b_koff = ((lane >> 3) & 1) * 16;     // bytes

    for (int s = 0; s < NKS; ++s) {
        CP_WAIT1();
        __syncthreads();
        if (s + 2 < NKS) load_stage(s + 2);
        CP_COMMIT();

        const uint32_t sa = smem + (s % STAGES) * STAGE_BYTES;
        const uint32_t sb = sa + B_OFF;
#pragma unroll
        for (int ks = 0; ks < BK / 16; ++ks) {
            uint32_t a[4][4], b[4][4];
#pragma unroll
            for (int mi = 0; mi < 4; ++mi)
                ldm_x4(a[mi], sa + (uint32_t)((a_row + mi * 16) * ROWB + ks * 32 + a_koff));
#pragma unroll
            for (int ni = 0; ni < 4; ++ni)
                ldm_x4(b[ni], sb + (uint32_t)((b_row + ni * 16) * ROWB + ks * 32 + b_koff));
#pragma unroll
            for (int mi = 0; mi < 4; ++mi)
#pragma unroll
                for (int ni = 0; ni < 4; ++ni) {
                    mma16816(c[mi][2 * ni + 0], a[mi], b[ni] + 0);
                    mma16816(c[mi][2 * ni + 1], a[mi], b[ni] + 2);
                }
        }
    }
}

// ---------------------------------------------------------------- Q projection
// acc -> QvA = pack_hl(acc+v), QuA = pack_hl(acc+u). M=ROWS, N=Dv (no guards).
__global__ void __launch_bounds__(256, 1) gemmQ_kernel(
    const __half* __restrict__ Aop, const __half* __restrict__ Bop,
    const float* __restrict__ vvec, const float* __restrict__ uvec,
    __half* __restrict__ QvA, __half* __restrict__ QuA)
{
    extern __shared__ uint8_t dsm[];
    const int brow = blockIdx.y * BM;
    const int bcol = blockIdx.x * BN;

    float c[4][8][4];
    gemm_core(Aop + (size_t)brow * K2, Bop + (size_t)bcol * K2, dsm, c);

    const int lane = threadIdx.x & 31, wid = threadIdx.x >> 5;
    const int wm = wid & 3, wn = wid >> 2;
#pragma unroll
    for (int mi = 0; mi < 4; ++mi) {
        const int r0 = brow + wm * 64 + mi * 16 + (lane >> 2);
#pragma unroll
        for (int half = 0; half < 2; ++half) {
            const int r = r0 + half * 8;
            __half* qv = QvA + (size_t)r * K2;
            __half* qu = QuA + (size_t)r * K2;
#pragma unroll
            for (int nj = 0; nj < 8; ++nj) {
                const int col = bcol + wn * 64 + nj * 8 + (lane & 3) * 2;
                const float a0 = c[mi][nj][half * 2 + 0];
                const float a1 = c[mi][nj][half * 2 + 1];
                const float2 vv = *reinterpret_cast<const float2*>(vvec + col);
                const float2 uu = *reinterpret_cast<const float2*>(uvec + col);
                // Qv
                {
                    const float q0 = a0 + vv.x, q1 = a1 + vv.y;
                    const __half h0 = __float2half_rn(q0), h1 = __float2half_rn(q1);
                    const __half l0 = __float2half_rn(q0 - __half2float(h0));
                    const __half l1 = __float2half_rn(q1 - __half2float(h1));
                    *reinterpret_cast<uint32_t*>(qv + col)      = hpack(h0, h1);
                    *reinterpret_cast<uint32_t*>(qv + Dv + col) = hpack(l0, l1);
                }
                // Qu
                {
                    const float q0 = a0 + uu.x, q1 = a1 + uu.y;
                    const __half h0 = __float2half_rn(q0), h1 = __float2half_rn(q1);
                    const __half l0 = __float2half_rn(q0 - __half2float(h0));
                    const __half l1 = __float2half_rn(q1 - __half2float(h1));
                    *reinterpret_cast<uint32_t*>(qu + col)      = hpack(h0, h1);
                    *reinterpret_cast<uint32_t*>(qu + Dv + col) = hpack(l0, l1);
                }
            }
        }
    }
}

// ---------------------------------------------------------------- K/R projection
// acc -> Bout = pack_hh(acc). Row guard for R (Mreal=TAB).
__global__ void __launch_bounds__(256, 1) gemmB_kernel(
    const __half* __restrict__ Aop, const __half* __restrict__ Bop,
    __half* __restrict__ Bout, int Mreal)
{
    extern __shared__ uint8_t dsm[];
    const int brow = blockIdx.y * BM;
    const int bcol = blockIdx.x * BN;

    float c[4][8][4];
    gemm_core(Aop + (size_t)brow * K2, Bop + (size_t)bcol * K2, dsm, c);

    const int lane = threadIdx.x & 31, wid = threadIdx.x >> 5;
    const int wm = wid & 3, wn = wid >> 2;
#pragma unroll
    for (int mi = 0; mi < 4; ++mi) {
        const int r0 = brow + wm * 64 + mi * 16 + (lane >> 2);
#pragma unroll
        for (int half = 0; half < 2; ++half) {
            const int r = r0 + half * 8;
            if (r >= Mreal) continue;
            __half* rb = Bout + (size_t)r * K2;
#pragma unroll
            for (int nj = 0; nj < 8; ++nj) {
                const int col = bcol + wn * 64 + nj * 8 + (lane & 3) * 2;
                const __half h0 = __float2half_rn(c[mi][nj][half * 2 + 0]);
                const __half h1 = __float2half_rn(c[mi][nj][half * 2 + 1]);
                const uint32_t hp = hpack(h0, h1);
                *reinterpret_cast<uint32_t*>(rb + col)      = hp;
                *reinterpret_cast<uint32_t*>(rb + Dv + col) = hp;
            }
        }
    }
}

// ---------------------------------------------------------------- fp32-out GEMM
__global__ void __launch_bounds__(256, 1) gemmF_kernel(
    const __half* __restrict__ Aop, const __half* __restrict__ Bop,
    float* __restrict__ C, int Nreal, int ldc)
{
    extern __shared__ uint8_t dsm[];
    const int brow = blockIdx.y * BM;
    const int bcol = blockIdx.x * BN;

    float c[4][8][4];
    gemm_core(Aop + (size_t)brow * K2, Bop + (size_t)bcol * K2, dsm, c);

    const int lane = threadIdx.x & 31, wid = threadIdx.x >> 5;
    const int wm = wid & 3, wn = wid >> 2;
#pragma unroll
    for (int mi = 0; mi < 4; ++mi) {
        const int r0 = brow + wm * 64 + mi * 16 + (lane >> 2);
#pragma unroll
        for (int half = 0; half < 2; ++half) {
            const int r = r0 + half * 8;
            float* crow = C + (size_t)r * ldc;
#pragma unroll
            for (int nj = 0; nj < 8; ++nj) {
                const int col = bcol + wn * 64 + nj * 8 + (lane & 3) * 2;
                const float v0 = c[mi][nj][half * 2 + 0];
                const float v1 = c[mi][nj][half * 2 + 1];
                if (col + 1 < Nreal) {
                    *reinterpret_cast<float2*>(crow + col) = make_float2(v0, v1);
                } else if (col < Nreal) {
                    crow[col] = v0;
                }
            }
        }
    }
}

// ---------------------------------------------------------------- content GEMM
// out[b,i,j] = (sum_d (Q+u)[b,i,d]*K[b,j,d] + SC[b,i, clip(i-j)+MR]) / 32
__global__ void __launch_bounds__(256, 1) content_kernel(
    const __half* __restrict__ QuA, const __half* __restrict__ KB,
    const float* __restrict__ SC, float* __restrict__ out)
{
    extern __shared__ uint8_t dsm[];
    const int b = blockIdx.z;
    const int brow = blockIdx.y * BM;
    const int bcol = blockIdx.x * BN;

    float c[4][8][4];
    gemm_core(QuA + ((size_t)(b * Lv + brow)) * K2,
              KB  + ((size_t)(b * Lv + bcol)) * K2, dsm, c);

    const int lane = threadIdx.x & 31, wid = threadIdx.x >> 5;
    const int wm = wid & 3, wn = wid >> 2;
    const float scale = 0.03125f;
#pragma unroll
    for (int mi = 0; mi < 4; ++mi) {
        const int r0 = brow + wm * 64 + mi * 16 + (lane >> 2);
#pragma unroll
        for (int half = 0; half < 2; ++half) {
            const int r = r0 + half * 8;
            const float* srow = SC + ((size_t)(b * Lv + r)) * LDSC;
            float* crow = out + ((size_t)b * Lv + r) * (size_t)Lv;
#pragma unroll
            for (int nj = 0; nj < 8; ++nj) {
                const int col = bcol + wn * 64 + nj * 8 + (lane & 3) * 2;
                int rel0 = r - col, rel1 = rel0 - 1;
                rel0 = rel0 < -MR ? -MR : (rel0 > MR ? MR : rel0);
                rel1 = rel1 < -MR ? -MR : (rel1 > MR ? MR : rel1);
                const float p0 = __ldg(&srow[rel0 + MR]);
                const float p1 = __ldg(&srow[rel1 + MR]);
                const float v0 = (c[mi][nj][half * 2 + 0] + p0) * scale;
                const float v1 = (c[mi][nj][half * 2 + 1] + p1) * scale;
                *reinterpret_cast<float2*>(crow + col) = make_float2(v0, v1);
            }
        }
    }
}

// ---------------------------------------------------------------- launch
extern "C" void kernel_launch(void* const* d_in, const int* in_sizes, int n_in,
                              void* d_out, int out_size)
{
    const float* x     = (const float*)d_in[0];
    const float* Wq    = (const float*)d_in[1];
    const float* Wk    = (const float*)d_in[2];
    const float* Wr    = (const float*)d_in[3];
    const float* u     = (const float*)d_in[4];
    const float* v     = (const float*)d_in[5];
    const float* table = (const float*)d_in[6];
    float* out = (float*)d_out;

    __half *xpA, *WqB, *WkB, *WrB, *tabA, *QvA, *QuA, *KB, *RB;
    float *SCp;
    cudaGetSymbolAddress((void**)&xpA, g_xpA);
    cudaGetSymbolAddress((void**)&WqB, g_WqB);
    cudaGetSymbolAddress((void**)&WkB, g_WkB);
    cudaGetSymbolAddress((void**)&WrB, g_WrB);
    cudaGetSymbolAddress((void**)&tabA, g_tabA);
    cudaGetSymbolAddress((void**)&QvA, g_QvA);
    cudaGetSymbolAddress((void**)&QuA, g_QuA);
    cudaGetSymbolAddress((void**)&KB, g_KB);
    cudaGetSymbolAddress((void**)&RB, g_RB);
    cudaGetSymbolAddress((void**)&SCp, g_SC);

    cudaFuncSetAttribute(gemmQ_kernel, cudaFuncAttributeMaxDynamicSharedMemorySize, SMEM_DYN);
    cudaFuncSetAttribute(gemmB_kernel, cudaFuncAttributeMaxDynamicSharedMemorySize, SMEM_DYN);
    cudaFuncSetAttribute(gemmF_kernel, cudaFuncAttributeMaxDynamicSharedMemorySize, SMEM_DYN);
    cudaFuncSetAttribute(content_kernel, cudaFuncAttributeMaxDynamicSharedMemorySize, SMEM_DYN);

    const dim3 pblk(256);
    const dim3 pgrd(1024);

    // Pack inputs (A-side [h|l] for x/table, B-side [h|h] for weights)
    pack_kernel<false><<<pgrd, pblk>>>(x, xpA, ROWS, ROWS);
    pack_kernel<true ><<<pgrd, pblk>>>(Wq, WqB, Dv, Dv);
    pack_kernel<true ><<<pgrd, pblk>>>(Wk, WkB, Dv, Dv);
    pack_kernel<true ><<<pgrd, pblk>>>(Wr, WrB, Dv, Dv);
    pack_kernel<false><<<pgrd, pblk>>>(table, tabA, TAB, TAB_PADM);

    // Q projection -> QvA, QuA packed (M=8192, N=1024)
    gemmQ_kernel<<<dim3(Dv / BN, ROWS / BM), 256, SMEM_DYN>>>(xpA, WqB, v, u, QvA, QuA);
    // K projection -> KB packed
    gemmB_kernel<<<dim3(Dv / BN, ROWS / BM), 256, SMEM_DYN>>>(xpA, WkB, KB, ROWS);
    // R projection -> RB packed (M=1025, pad rows stay zero-initialized)
    gemmB_kernel<<<dim3(Dv / BN, TAB_PADM / BM), 256, SMEM_DYN>>>(tabA, WrB, RB, TAB);

    // A_scores = (Q+v) R^T (M=8192, N=1025 padded to 1152, ldc=1028)
    gemmF_kernel<<<dim3(TAB_PADN / BN, ROWS / BM), 256, SMEM_DYN>>>(QvA, RB, SCp, TAB, LDSC);

    // content + gather + scale (per batch 2048x2048)
    content_kernel<<<dim3(Lv / BN, Lv / BM, Bv), 256, SMEM_DYN>>>(QuA, KB, SCp, out);

    (void)in_sizes; (void)n_in; (void)out_size;
}